// round 7
// baseline (speedup 1.0000x reference)
#include <cuda_runtime.h>
#include <cuda_bf16.h>

// Problem constants (fixed shapes for BevPoolV2_8478265442577)
#define B_     1
#define N_CAM  6
#define D_BINS 118
#define HF     32
#define WF     88
#define C_     80
#define DZ     1
#define DY     128
#define DX     128

#define N_DEPTH (B_ * N_CAM * D_BINS * HF * WF)   // 1,993,728
#define N_FEAT  (B_ * N_CAM * HF * WF * C_)       // 1,351,680
#define N_PTS   1000000
#define S_      (DZ * DY * DX)                    // 16,384

// ---------------------------------------------------------------------------
// Zero-init the output (harness poisons d_out with 0xAA; empty bins must be 0)
// ---------------------------------------------------------------------------
__global__ void zero_kernel(float4* __restrict__ out, int n4) {
    int i = blockIdx.x * blockDim.x + threadIdx.x;
    int stride = gridDim.x * blockDim.x;
    for (; i < n4; i += stride)
        out[i] = make_float4(0.f, 0.f, 0.f, 0.f);
}

// ---------------------------------------------------------------------------
// TWO intervals per warp (independent dependency chains -> 2x MLP).
// Lane l (0..19) owns channels [4l, 4l+4) as a float4 for BOTH intervals.
// Per 16-point chunk per stream:
//   - 1 LDG: lanes 0-15 read ranks_depth, lanes 16-31 read ranks_feat
//     (predicated; out-of-range points padded with d=0, rf=0)
//   - 1 LDG: lanes 0-15 gather the 16 depth scalars
//   - inner loop: 4 points per stream per group -> 8 independent LDG.128
// Intervals are disjoint BEV bins -> plain stores, no atomics.
// ---------------------------------------------------------------------------
__global__ void __launch_bounds__(256)
bev_pool_kernel(const float* __restrict__ depth,
                const float* __restrict__ feat,
                const int*   __restrict__ ranks_depth,
                const int*   __restrict__ ranks_feat,
                const int*   __restrict__ ranks_bev,
                const int*   __restrict__ istart,
                const int*   __restrict__ ilen,
                int n_intervals,
                float* __restrict__ out) {
    const int lane  = threadIdx.x & 31;
    const int gpair = (blockIdx.x * blockDim.x + threadIdx.x) >> 5;
    const int g0 = gpair * 2;
    const int g1 = g0 + 1;
    if (g0 >= n_intervals) return;

    const int  start0 = istart[g0];
    const int  len0   = ilen[g0];
    const bool has1   = (g1 < n_intervals);
    const int  start1 = has1 ? istart[g1] : 0;
    const int  len1   = has1 ? ilen[g1]   : 0;

    const bool fa   = (lane < 20);               // feat-active lanes (20*4 = 80 ch)
    const int  lo16 = lane & 15;
    const float4* __restrict__ fbase = (const float4*)feat;

    float4 acc0 = make_float4(0.f, 0.f, 0.f, 0.f);
    float4 acc1 = make_float4(0.f, 0.f, 0.f, 0.f);

    const int nch = max((len0 + 15) >> 4, (len1 + 15) >> 4);

    for (int ch = 0; ch < nch; ch++) {
        const int base = ch * 16;

        // ---- stream 0 scalars (predicated; padded points -> d=0, rf=0) ----
        int   idx0 = 0;
        float dv0  = 0.f;
        if (lo16 < len0 - base) {
            const int p = start0 + base + lo16;
            idx0 = (lane < 16) ? __ldg(ranks_depth + p) : __ldg(ranks_feat + p);
            if (lane < 16) dv0 = __ldg(&depth[idx0]);
        }

        // ---- stream 1 scalars (independent chain) ----
        int   idx1 = 0;
        float dv1  = 0.f;
        if (lo16 < len1 - base) {
            const int p = start1 + base + lo16;
            idx1 = (lane < 16) ? __ldg(ranks_depth + p) : __ldg(ranks_feat + p);
            if (lane < 16) dv1 = __ldg(&depth[idx1]);
        }

        #pragma unroll
        for (int j = 0; j < 16; j += 4) {
            // broadcast 4 points per stream (two independent shuffle sets)
            float a0 = __shfl_sync(0xffffffffu, dv0, j + 0);
            float a1 = __shfl_sync(0xffffffffu, dv0, j + 1);
            float a2 = __shfl_sync(0xffffffffu, dv0, j + 2);
            float a3 = __shfl_sync(0xffffffffu, dv0, j + 3);
            int r0 = __shfl_sync(0xffffffffu, idx0, 16 + j + 0);
            int r1 = __shfl_sync(0xffffffffu, idx0, 16 + j + 1);
            int r2 = __shfl_sync(0xffffffffu, idx0, 16 + j + 2);
            int r3 = __shfl_sync(0xffffffffu, idx0, 16 + j + 3);
            float b0 = __shfl_sync(0xffffffffu, dv1, j + 0);
            float b1 = __shfl_sync(0xffffffffu, dv1, j + 1);
            float b2 = __shfl_sync(0xffffffffu, dv1, j + 2);
            float b3 = __shfl_sync(0xffffffffu, dv1, j + 3);
            int s0 = __shfl_sync(0xffffffffu, idx1, 16 + j + 0);
            int s1 = __shfl_sync(0xffffffffu, idx1, 16 + j + 1);
            int s2 = __shfl_sync(0xffffffffu, idx1, 16 + j + 2);
            int s3 = __shfl_sync(0xffffffffu, idx1, 16 + j + 3);
            if (fa) {
                // 8 independent 128-bit gathers in flight
                float4 f0 = __ldg(fbase + (size_t)r0 * 20 + lane);
                float4 f1 = __ldg(fbase + (size_t)r1 * 20 + lane);
                float4 f2 = __ldg(fbase + (size_t)r2 * 20 + lane);
                float4 f3 = __ldg(fbase + (size_t)r3 * 20 + lane);
                float4 h0 = __ldg(fbase + (size_t)s0 * 20 + lane);
                float4 h1 = __ldg(fbase + (size_t)s1 * 20 + lane);
                float4 h2 = __ldg(fbase + (size_t)s2 * 20 + lane);
                float4 h3 = __ldg(fbase + (size_t)s3 * 20 + lane);
                acc0.x = fmaf(a0, f0.x, acc0.x);
                acc0.y = fmaf(a0, f0.y, acc0.y);
                acc0.z = fmaf(a0, f0.z, acc0.z);
                acc0.w = fmaf(a0, f0.w, acc0.w);
                acc1.x = fmaf(b0, h0.x, acc1.x);
                acc1.y = fmaf(b0, h0.y, acc1.y);
                acc1.z = fmaf(b0, h0.z, acc1.z);
                acc1.w = fmaf(b0, h0.w, acc1.w);
                acc0.x = fmaf(a1, f1.x, acc0.x);
                acc0.y = fmaf(a1, f1.y, acc0.y);
                acc0.z = fmaf(a1, f1.z, acc0.z);
                acc0.w = fmaf(a1, f1.w, acc0.w);
                acc1.x = fmaf(b1, h1.x, acc1.x);
                acc1.y = fmaf(b1, h1.y, acc1.y);
                acc1.z = fmaf(b1, h1.z, acc1.z);
                acc1.w = fmaf(b1, h1.w, acc1.w);
                acc0.x = fmaf(a2, f2.x, acc0.x);
                acc0.y = fmaf(a2, f2.y, acc0.y);
                acc0.z = fmaf(a2, f2.z, acc0.z);
                acc0.w = fmaf(a2, f2.w, acc0.w);
                acc1.x = fmaf(b2, h2.x, acc1.x);
                acc1.y = fmaf(b2, h2.y, acc1.y);
                acc1.z = fmaf(b2, h2.z, acc1.z);
                acc1.w = fmaf(b2, h2.w, acc1.w);
                acc0.x = fmaf(a3, f3.x, acc0.x);
                acc0.y = fmaf(a3, f3.y, acc0.y);
                acc0.z = fmaf(a3, f3.z, acc0.z);
                acc0.w = fmaf(a3, f3.w, acc0.w);
                acc1.x = fmaf(b3, h3.x, acc1.x);
                acc1.y = fmaf(b3, h3.y, acc1.y);
                acc1.z = fmaf(b3, h3.z, acc1.z);
                acc1.w = fmaf(b3, h3.w, acc1.w);
            }
        }
    }

    // ---- stores: output layout (B, C, Dz, Dy, Dx); bev = b*S + s ----
    if (fa) {
        const int c = lane * 4;
        {
            int bev = __ldg(&ranks_bev[start0]);
            int b   = bev / S_;
            int s   = bev - b * S_;
            float* o = out + (size_t)b * C_ * S_ + s;
            o[(size_t)(c + 0) * S_] = acc0.x;
            o[(size_t)(c + 1) * S_] = acc0.y;
            o[(size_t)(c + 2) * S_] = acc0.z;
            o[(size_t)(c + 3) * S_] = acc0.w;
        }
        if (has1) {
            int bev = __ldg(&ranks_bev[start1]);
            int b   = bev / S_;
            int s   = bev - b * S_;
            float* o = out + (size_t)b * C_ * S_ + s;
            o[(size_t)(c + 0) * S_] = acc1.x;
            o[(size_t)(c + 1) * S_] = acc1.y;
            o[(size_t)(c + 2) * S_] = acc1.z;
            o[(size_t)(c + 3) * S_] = acc1.w;
        }
    }
}

// ---------------------------------------------------------------------------
extern "C" void kernel_launch(void* const* d_in, const int* in_sizes, int n_in,
                              void* d_out, int out_size) {
    const float* depth = nullptr;
    const float* feat  = nullptr;
    const int*   ranks[3] = {nullptr, nullptr, nullptr};
    int nrk = 0;
    const int* small_arr[2] = {nullptr, nullptr};
    int small_sz[2] = {0, 0};
    int nsmall = 0;

    for (int i = 0; i < n_in; i++) {
        int sz = in_sizes[i];
        if (sz == N_DEPTH && !depth) {
            depth = (const float*)d_in[i];
        } else if (sz == N_FEAT && !feat) {
            feat = (const float*)d_in[i];
        } else if (sz == N_PTS && nrk < 3) {
            ranks[nrk++] = (const int*)d_in[i];   // order: depths, feats, bevs
        } else if (sz == 5) {
            // bev_feat_shape metadata — compile-time constants here
        } else if (nsmall < 2) {
            small_arr[nsmall] = (const int*)d_in[i];  // order: starts, lengths
            small_sz[nsmall] = sz;
            nsmall++;
        }
    }

    const int* istart = small_arr[0];
    const int* ilen   = small_arr[1];
    int n_intervals   = small_sz[0];

    float* out = (float*)d_out;

    // 1) zero the output
    int n4 = out_size / 4;
    zero_kernel<<<256, 256>>>((float4*)out, n4);

    // 2) pooled gather-multiply-store, two intervals per warp
    const int threads = 256;                    // 8 warps per block
    int n_pairs = (n_intervals + 1) / 2;
    int blocks = (n_pairs + 7) / 8;
    if (blocks < 1) blocks = 1;
    bev_pool_kernel<<<blocks, threads>>>(depth, feat,
                                         ranks[0], ranks[1], ranks[2],
                                         istart, ilen, n_intervals, out);
}

// round 8
// speedup vs baseline: 1.2740x; 1.2740x over previous
#include <cuda_runtime.h>
#include <cuda_bf16.h>
#include <cuda_fp16.h>

// Problem constants (fixed shapes for BevPoolV2_8478265442577)
#define B_     1
#define N_CAM  6
#define D_BINS 118
#define HF     32
#define WF     88
#define C_     80
#define DZ     1
#define DY     128
#define DX     128

#define N_DEPTH (B_ * N_CAM * D_BINS * HF * WF)   // 1,993,728
#define N_FEAT  (B_ * N_CAM * HF * WF * C_)       // 1,351,680
#define N_PTS   1000000
#define S_      (DZ * DY * DX)                    // 16,384

// fp16 mirror of feat: 80 halves per row = 160 B per row (20 x uint2)
__device__ __align__(16) static __half g_feat16[N_FEAT];

// ---------------------------------------------------------------------------
// Zero-init the output (harness poisons d_out with 0xAA; empty bins must be 0)
// ---------------------------------------------------------------------------
__global__ void zero_kernel(float4* __restrict__ out, int n4) {
    int i = blockIdx.x * blockDim.x + threadIdx.x;
    int stride = gridDim.x * blockDim.x;
    for (; i < n4; i += stride)
        out[i] = make_float4(0.f, 0.f, 0.f, 0.f);
}

// ---------------------------------------------------------------------------
// Convert feat fp32 -> fp16 mirror (runs every launch; ~8 MB of traffic)
// ---------------------------------------------------------------------------
__global__ void cvt_kernel(const float4* __restrict__ src, int n4) {
    uint2* __restrict__ dst = (uint2*)g_feat16;
    int i = blockIdx.x * blockDim.x + threadIdx.x;
    int stride = gridDim.x * blockDim.x;
    for (; i < n4; i += stride) {
        float4 v = src[i];
        __half2 h0 = __floats2half2_rn(v.x, v.y);
        __half2 h1 = __floats2half2_rn(v.z, v.w);
        uint2 u;
        u.x = *reinterpret_cast<unsigned int*>(&h0);
        u.y = *reinterpret_cast<unsigned int*>(&h1);
        dst[i] = u;
    }
}

// ---------------------------------------------------------------------------
// One warp per interval. Lane l (0..19) owns channels [4l, 4l+4).
// Per 16-point chunk:
//   - 1 LDG: lanes 0-15 read ranks_depth, lanes 16-31 read ranks_feat
//   - 1 LDG: lanes 0-15 gather the 16 depth scalars
//   - inner loop 4 points per group -> 4 independent LDG.64 (fp16 feat)
// Intervals are disjoint BEV bins -> plain stores, no atomics.
// ---------------------------------------------------------------------------
__global__ void __launch_bounds__(256)
bev_pool_kernel(const float* __restrict__ depth,
                const int*   __restrict__ ranks_depth,
                const int*   __restrict__ ranks_feat,
                const int*   __restrict__ ranks_bev,
                const int*   __restrict__ istart,
                const int*   __restrict__ ilen,
                int n_intervals,
                float* __restrict__ out) {
    int gwarp = (blockIdx.x * blockDim.x + threadIdx.x) >> 5;
    int lane  = threadIdx.x & 31;
    if (gwarp >= n_intervals) return;

    const int start = istart[gwarp];
    const int len   = ilen[gwarp];

    const bool fa = (lane < 20);                 // feat-active lanes (20*4 = 80 ch)
    const uint2* __restrict__ fbase = (const uint2*)g_feat16;  // row stride 20

    float4 acc = make_float4(0.f, 0.f, 0.f, 0.f);

    const int lo16  = lane & 15;
    const int nfull = len & ~15;

    int i = 0;
    for (; i < nfull; i += 16) {
        const int p = start + i;
        const int* ip = (lane < 16) ? (ranks_depth + p + lane)
                                    : (ranks_feat  + p + lo16);
        int idxv = __ldg(ip);
        float dv = 0.f;
        if (lane < 16) dv = __ldg(&depth[idxv]);

        #pragma unroll
        for (int j = 0; j < 16; j += 4) {
            float d0 = __shfl_sync(0xffffffffu, dv, j + 0);
            float d1 = __shfl_sync(0xffffffffu, dv, j + 1);
            float d2 = __shfl_sync(0xffffffffu, dv, j + 2);
            float d3 = __shfl_sync(0xffffffffu, dv, j + 3);
            int rf0 = __shfl_sync(0xffffffffu, idxv, 16 + j + 0);
            int rf1 = __shfl_sync(0xffffffffu, idxv, 16 + j + 1);
            int rf2 = __shfl_sync(0xffffffffu, idxv, 16 + j + 2);
            int rf3 = __shfl_sync(0xffffffffu, idxv, 16 + j + 3);
            if (fa) {
                // 4 independent 64-bit fp16 gathers in flight
                uint2 u0 = __ldg(fbase + (size_t)rf0 * 20 + lane);
                uint2 u1 = __ldg(fbase + (size_t)rf1 * 20 + lane);
                uint2 u2 = __ldg(fbase + (size_t)rf2 * 20 + lane);
                uint2 u3 = __ldg(fbase + (size_t)rf3 * 20 + lane);

                float2 a0 = __half22float2(*reinterpret_cast<__half2*>(&u0.x));
                float2 b0 = __half22float2(*reinterpret_cast<__half2*>(&u0.y));
                float2 a1 = __half22float2(*reinterpret_cast<__half2*>(&u1.x));
                float2 b1 = __half22float2(*reinterpret_cast<__half2*>(&u1.y));
                float2 a2 = __half22float2(*reinterpret_cast<__half2*>(&u2.x));
                float2 b2 = __half22float2(*reinterpret_cast<__half2*>(&u2.y));
                float2 a3 = __half22float2(*reinterpret_cast<__half2*>(&u3.x));
                float2 b3 = __half22float2(*reinterpret_cast<__half2*>(&u3.y));

                acc.x = fmaf(d0, a0.x, acc.x);
                acc.y = fmaf(d0, a0.y, acc.y);
                acc.z = fmaf(d0, b0.x, acc.z);
                acc.w = fmaf(d0, b0.y, acc.w);
                acc.x = fmaf(d1, a1.x, acc.x);
                acc.y = fmaf(d1, a1.y, acc.y);
                acc.z = fmaf(d1, b1.x, acc.z);
                acc.w = fmaf(d1, b1.y, acc.w);
                acc.x = fmaf(d2, a2.x, acc.x);
                acc.y = fmaf(d2, a2.y, acc.y);
                acc.z = fmaf(d2, b2.x, acc.z);
                acc.w = fmaf(d2, b2.y, acc.w);
                acc.x = fmaf(d3, a3.x, acc.x);
                acc.y = fmaf(d3, a3.y, acc.y);
                acc.z = fmaf(d3, b3.x, acc.z);
                acc.w = fmaf(d3, b3.y, acc.w);
            }
        }
    }

    // ---- tail chunk (< 16 points) ----
    if (i < len) {
        const int n = len - i;
        const int p = start + i;
        bool valid = lo16 < n;
        const int* ip = (lane < 16) ? (ranks_depth + p + lo16)
                                    : (ranks_feat  + p + lo16);
        int ti = valid ? __ldg(ip) : 0;
        float td = 0.f;
        if (lane < 16 && valid) td = __ldg(&depth[ti]);

        for (int j = 0; j < n; j++) {
            float d  = __shfl_sync(0xffffffffu, td, j);
            int   rf = __shfl_sync(0xffffffffu, ti, 16 + j);
            if (fa) {
                uint2 u = __ldg(fbase + (size_t)rf * 20 + lane);
                float2 a = __half22float2(*reinterpret_cast<__half2*>(&u.x));
                float2 b = __half22float2(*reinterpret_cast<__half2*>(&u.y));
                acc.x = fmaf(d, a.x, acc.x);
                acc.y = fmaf(d, a.y, acc.y);
                acc.z = fmaf(d, b.x, acc.z);
                acc.w = fmaf(d, b.y, acc.w);
            }
        }
    }

    // ---- store: output layout (B, C, Dz, Dy, Dx); bev = b*S + s ----
    if (fa) {
        int bev = __ldg(&ranks_bev[start]);
        int b   = bev / S_;
        int s   = bev - b * S_;
        float* o = out + (size_t)b * C_ * S_ + s;
        int c = lane * 4;
        o[(size_t)(c + 0) * S_] = acc.x;
        o[(size_t)(c + 1) * S_] = acc.y;
        o[(size_t)(c + 2) * S_] = acc.z;
        o[(size_t)(c + 3) * S_] = acc.w;
    }
}

// ---------------------------------------------------------------------------
extern "C" void kernel_launch(void* const* d_in, const int* in_sizes, int n_in,
                              void* d_out, int out_size) {
    const float* depth = nullptr;
    const float* feat  = nullptr;
    const int*   ranks[3] = {nullptr, nullptr, nullptr};
    int nrk = 0;
    const int* small_arr[2] = {nullptr, nullptr};
    int small_sz[2] = {0, 0};
    int nsmall = 0;

    for (int i = 0; i < n_in; i++) {
        int sz = in_sizes[i];
        if (sz == N_DEPTH && !depth) {
            depth = (const float*)d_in[i];
        } else if (sz == N_FEAT && !feat) {
            feat = (const float*)d_in[i];
        } else if (sz == N_PTS && nrk < 3) {
            ranks[nrk++] = (const int*)d_in[i];   // order: depths, feats, bevs
        } else if (sz == 5) {
            // bev_feat_shape metadata — compile-time constants here
        } else if (nsmall < 2) {
            small_arr[nsmall] = (const int*)d_in[i];  // order: starts, lengths
            small_sz[nsmall] = sz;
            nsmall++;
        }
    }

    const int* istart = small_arr[0];
    const int* ilen   = small_arr[1];
    int n_intervals   = small_sz[0];

    float* out = (float*)d_out;

    // 1) zero the output
    int n4 = out_size / 4;
    zero_kernel<<<256, 256>>>((float4*)out, n4);

    // 2) convert feat fp32 -> fp16 mirror
    cvt_kernel<<<256, 256>>>((const float4*)feat, N_FEAT / 4);

    // 3) pooled gather-multiply-store, one warp per interval
    const int threads = 256;                    // 8 warps per block
    int blocks = (n_intervals + 7) / 8;
    if (blocks < 1) blocks = 1;
    bev_pool_kernel<<<blocks, threads>>>(depth,
                                         ranks[0], ranks[1], ranks[2],
                                         istart, ilen, n_intervals, out);
}